// round 1
// baseline (speedup 1.0000x reference)
#include <cuda_runtime.h>
#include <math.h>

// Problem constants
#define BB 4
#define TT 2048
#define DD 1024
#define HH 16
#define DH 64
#define MTOT (BB*TT)        // 8192
#define N_QKV (3*DD)        // 3072

// Scratch (device globals: allocation-guard safe)
__device__ float g_qkv[(size_t)MTOT * N_QKV];   // [8192, 3072]
__device__ float g_attn[(size_t)MTOT * DD];     // [8192, 1024]

// ---------------------------------------------------------------------------
// SGEMM with bias: C[M,N] = A[M,K] @ B[K,N] + bias[N]
// BM=128, BN=128, BK=16, 256 threads, 8x8 per-thread tile.
// Requires M%128==0, N%128==0, K%16==0 (true for all our shapes).
// ---------------------------------------------------------------------------
__global__ __launch_bounds__(256, 2)
void sgemm_bias_kernel(const float* __restrict__ A, const float* __restrict__ B,
                       const float* __restrict__ bias, float* __restrict__ C,
                       int M, int N, int K)
{
    const int BK = 16;
    __shared__ float As[16][132];   // transposed A tile, +4 pad
    __shared__ float Bs[16][128];

    const int tid  = threadIdx.x;
    const int bm0  = blockIdx.y * 128;
    const int bn0  = blockIdx.x * 128;
    const int wid  = tid >> 5;
    const int lane = tid & 31;
    // warp grid 4x2 (32x64 per warp), lane grid 4x8 (8x8 per thread)
    const int row0 = (wid >> 1) * 32 + (lane >> 3) * 8;
    const int col0 = (wid & 1) * 64 + (lane & 7) * 8;

    float acc[8][8];
    #pragma unroll
    for (int i = 0; i < 8; i++)
        #pragma unroll
        for (int j = 0; j < 8; j++) acc[i][j] = 0.0f;

    for (int k0 = 0; k0 < K; k0 += BK) {
        // Load A tile (128x16), store transposed
        #pragma unroll
        for (int i = 0; i < 2; i++) {
            int f = tid + i * 256;           // 0..511
            int r = f >> 2;                  // 0..127
            int kc = (f & 3) * 4;            // 0,4,8,12
            float4 v = *(const float4*)&A[(size_t)(bm0 + r) * K + k0 + kc];
            As[kc + 0][r] = v.x;
            As[kc + 1][r] = v.y;
            As[kc + 2][r] = v.z;
            As[kc + 3][r] = v.w;
        }
        // Load B tile (16x128)
        #pragma unroll
        for (int i = 0; i < 2; i++) {
            int f = tid + i * 256;           // 0..511
            int r = f >> 5;                  // 0..15
            int c = (f & 31) * 4;            // 0..124
            *(float4*)&Bs[r][c] = *(const float4*)&B[(size_t)(k0 + r) * N + bn0 + c];
        }
        __syncthreads();

        #pragma unroll
        for (int k = 0; k < BK; k++) {
            float a[8], b[8];
            *(float4*)&a[0] = *(const float4*)&As[k][row0];
            *(float4*)&a[4] = *(const float4*)&As[k][row0 + 4];
            *(float4*)&b[0] = *(const float4*)&Bs[k][col0];
            *(float4*)&b[4] = *(const float4*)&Bs[k][col0 + 4];
            #pragma unroll
            for (int i = 0; i < 8; i++)
                #pragma unroll
                for (int j = 0; j < 8; j++)
                    acc[i][j] += a[i] * b[j];
        }
        __syncthreads();
    }

    // Epilogue: add bias, store
    float bb[8];
    #pragma unroll
    for (int j = 0; j < 8; j++) bb[j] = bias[bn0 + col0 + j];

    #pragma unroll
    for (int i = 0; i < 8; i++) {
        size_t off = (size_t)(bm0 + row0 + i) * N + bn0 + col0;
        float4 o0, o1;
        o0.x = acc[i][0] + bb[0]; o0.y = acc[i][1] + bb[1];
        o0.z = acc[i][2] + bb[2]; o0.w = acc[i][3] + bb[3];
        o1.x = acc[i][4] + bb[4]; o1.y = acc[i][5] + bb[5];
        o1.z = acc[i][6] + bb[6]; o1.w = acc[i][7] + bb[7];
        *(float4*)&C[off]     = o0;
        *(float4*)&C[off + 4] = o1;
    }
}

// ---------------------------------------------------------------------------
// Flash attention (fp32, non-causal, key mask):
//   per (b,h), per 64-row Q tile: online softmax over 32 K/V tiles of 64.
//   scores = QK^T / 8; masked entries set to exactly -1000.0f (matches ref).
// grid = (T/64, B*H), 256 threads.
// Dynamic smem: Qs[64][64], Ks[64][65], Vs[64][64], Ps[64][64], msk[64]
// ---------------------------------------------------------------------------
#define ATTN_SMEM_BYTES ((64*64 + 64*65 + 64*64 + 64*64) * 4 + 64 * 4)

__global__ __launch_bounds__(256)
void attn_kernel(const float* __restrict__ qkv, const int* __restrict__ mask,
                 float* __restrict__ out)
{
    extern __shared__ float sm[];
    float* Qs = sm;                    // [64][64]
    float* Ks = Qs + 64 * 64;          // [64][65]  (pad avoids strided-read conflicts)
    float* Vs = Ks + 64 * 65;          // [64][64]
    float* Ps = Vs + 64 * 64;          // [64][64]
    int*  msk = (int*)(Ps + 64 * 64);  // [64]

    const int tid  = threadIdx.x;
    const int lane = tid & 31;
    const int wid  = tid >> 5;
    const int bh = blockIdx.y;
    const int b  = bh >> 4;
    const int h  = bh & 15;
    const int t0 = blockIdx.x * 64;

    // thread tile: rows mrow0..mrow0+3, cols nc0..nc0+3 of the 64x64 S tile
    const int mrow0 = wid * 8 + (lane >> 4) * 4;
    const int nc0   = (lane & 15) * 4;

    const size_t base = (size_t)b * TT * N_QKV + (size_t)h * DH;

    // Load Q tile (64 rows x 64 dims)
    #pragma unroll
    for (int i = 0; i < 4; i++) {
        int f = tid + i * 256;          // 0..1023
        int m = f >> 4;                 // 0..63
        int d4 = (f & 15) * 4;          // 0..60
        *(float4*)&Qs[m * 64 + d4] =
            *(const float4*)&qkv[base + (size_t)(t0 + m) * N_QKV + d4];
    }

    float m_i[4], l_i[4], o[4][4];
    #pragma unroll
    for (int i = 0; i < 4; i++) {
        m_i[i] = -3.0e38f;
        l_i[i] = 0.0f;
        #pragma unroll
        for (int j = 0; j < 4; j++) o[i][j] = 0.0f;
    }

    for (int n0 = 0; n0 < TT; n0 += 64) {
        __syncthreads();  // protect Ks/Vs from previous tile's PV readers

        // Load K, V tiles + mask
        #pragma unroll
        for (int i = 0; i < 4; i++) {
            int f = tid + i * 256;
            int m = f >> 4;
            int d4 = (f & 15) * 4;
            float4 kv = *(const float4*)&qkv[base + DD + (size_t)(n0 + m) * N_QKV + d4];
            Ks[m * 65 + d4 + 0] = kv.x;
            Ks[m * 65 + d4 + 1] = kv.y;
            Ks[m * 65 + d4 + 2] = kv.z;
            Ks[m * 65 + d4 + 3] = kv.w;
            *(float4*)&Vs[m * 64 + d4] =
                *(const float4*)&qkv[base + 2 * DD + (size_t)(n0 + m) * N_QKV + d4];
        }
        if (tid < 64) msk[tid] = mask[b * TT + n0 + tid];
        __syncthreads();

        // S = Q K^T (64x64x64)
        float acc[4][4];
        #pragma unroll
        for (int i = 0; i < 4; i++)
            #pragma unroll
            for (int j = 0; j < 4; j++) acc[i][j] = 0.0f;

        #pragma unroll 8
        for (int d = 0; d < DH; d++) {
            float a[4], bb[4];
            #pragma unroll
            for (int i = 0; i < 4; i++) a[i]  = Qs[(mrow0 + i) * 64 + d];
            #pragma unroll
            for (int j = 0; j < 4; j++) bb[j] = Ks[(nc0 + j) * 65 + d];
            #pragma unroll
            for (int i = 0; i < 4; i++)
                #pragma unroll
                for (int j = 0; j < 4; j++)
                    acc[i][j] += a[i] * bb[j];
        }

        // scale + mask (exactly -1000.0f on masked, matching reference)
        int mk[4];
        #pragma unroll
        for (int j = 0; j < 4; j++) mk[j] = msk[nc0 + j];

        // online softmax per row (row spread over 16 lanes: shfl_xor 1..8)
        #pragma unroll
        for (int i = 0; i < 4; i++) {
            float tm = -3.0e38f;
            #pragma unroll
            for (int j = 0; j < 4; j++) {
                float s = mk[j] ? acc[i][j] * 0.125f : -1000.0f;
                acc[i][j] = s;
                tm = fmaxf(tm, s);
            }
            #pragma unroll
            for (int off = 1; off < 16; off <<= 1)
                tm = fmaxf(tm, __shfl_xor_sync(0xffffffffu, tm, off));

            float mn = fmaxf(m_i[i], tm);
            float alpha = __expf(m_i[i] - mn);
            m_i[i] = mn;

            float rs = 0.0f;
            float p0 = __expf(acc[i][0] - mn);
            float p1 = __expf(acc[i][1] - mn);
            float p2 = __expf(acc[i][2] - mn);
            float p3 = __expf(acc[i][3] - mn);
            rs = p0 + p1 + p2 + p3;
            #pragma unroll
            for (int off = 1; off < 16; off <<= 1)
                rs += __shfl_xor_sync(0xffffffffu, rs, off);

            l_i[i] = l_i[i] * alpha + rs;
            #pragma unroll
            for (int j = 0; j < 4; j++) o[i][j] *= alpha;

            float4 pv; pv.x = p0; pv.y = p1; pv.z = p2; pv.w = p3;
            *(float4*)&Ps[(mrow0 + i) * 64 + nc0] = pv;
        }
        __syncthreads();

        // O += P V (64x64x64); thread owns O rows mrow0.., dims nc0..
        #pragma unroll 8
        for (int n = 0; n < 64; n++) {
            float a[4];
            #pragma unroll
            for (int i = 0; i < 4; i++) a[i] = Ps[(mrow0 + i) * 64 + n];
            float4 v = *(const float4*)&Vs[n * 64 + nc0];
            #pragma unroll
            for (int i = 0; i < 4; i++) {
                o[i][0] += a[i] * v.x;
                o[i][1] += a[i] * v.y;
                o[i][2] += a[i] * v.z;
                o[i][3] += a[i] * v.w;
            }
        }
    }

    // Normalize and write: out[(b*T + t0+m)*D + h*64 + d]
    #pragma unroll
    for (int i = 0; i < 4; i++) {
        float inv = 1.0f / l_i[i];
        float4 ov;
        ov.x = o[i][0] * inv; ov.y = o[i][1] * inv;
        ov.z = o[i][2] * inv; ov.w = o[i][3] * inv;
        size_t off = (size_t)(b * TT + t0 + mrow0 + i) * DD + h * DH + nc0;
        *(float4*)&out[off] = ov;
    }
}

// ---------------------------------------------------------------------------
extern "C" void kernel_launch(void* const* d_in, const int* in_sizes, int n_in,
                              void* d_out, int out_size)
{
    const float* x     = (const float*)d_in[0];   // [4,2048,1024]
    const int*   mask  = (const int*)  d_in[1];   // [4,1,1,2048]
    const float* W_qkv = (const float*)d_in[2];   // [1024,3072]
    const float* b_qkv = (const float*)d_in[3];   // [3072]
    const float* W_out = (const float*)d_in[4];   // [1024,1024]
    const float* b_out = (const float*)d_in[5];   // [1024]
    float* out = (float*)d_out;                   // [4,2048,1024]

    float* qkv  = nullptr;
    float* attn = nullptr;
    cudaGetSymbolAddress((void**)&qkv,  g_qkv);
    cudaGetSymbolAddress((void**)&attn, g_attn);

    cudaFuncSetAttribute(attn_kernel,
                         cudaFuncAttributeMaxDynamicSharedMemorySize,
                         ATTN_SMEM_BYTES);

    // 1) QKV projection: [8192,1024] @ [1024,3072] + b
    sgemm_bias_kernel<<<dim3(N_QKV / 128, MTOT / 128), 256>>>(
        x, W_qkv, b_qkv, qkv, MTOT, N_QKV, DD);

    // 2) Attention
    attn_kernel<<<dim3(TT / 64, BB * HH), 256, ATTN_SMEM_BYTES>>>(qkv, mask, attn);

    // 3) Output projection: [8192,1024] @ [1024,1024] + b
    sgemm_bias_kernel<<<dim3(DD / 128, MTOT / 128), 256>>>(
        attn, W_out, b_out, out, MTOT, DD, DD);
}

// round 4
// speedup vs baseline: 1.3405x; 1.3405x over previous
#include <cuda_runtime.h>
#include <cuda_bf16.h>
#include <cstdint>
#include <math.h>

// Problem constants
#define BB 4
#define TT 2048
#define DD 1024
#define HH 16
#define DH 64
#define MTOT (BB*TT)        // 8192
#define N_QKV (3*DD)        // 3072

// Scratch (device globals: allocation-guard safe)
__device__ float g_qkv[(size_t)MTOT * N_QKV];   // [8192, 3072]
__device__ float g_attn[(size_t)MTOT * DD];     // [8192, 1024]
__device__ __nv_bfloat16 g_wqkv_h[(size_t)N_QKV * DD];  // W_qkv^T hi  [3072,1024]
__device__ __nv_bfloat16 g_wqkv_l[(size_t)N_QKV * DD];  // W_qkv^T lo
__device__ __nv_bfloat16 g_wout_h[(size_t)DD * DD];     // W_out^T hi  [1024,1024]
__device__ __nv_bfloat16 g_wout_l[(size_t)DD * DD];     // W_out^T lo
__device__ __nv_bfloat16 g_act_h[(size_t)MTOT * DD];    // activation hi [M,K]
__device__ __nv_bfloat16 g_act_l[(size_t)MTOT * DD];    // activation lo

// ---------------------------------------------------------------------------
// sm_80-portable PTX helpers: mma.sync / ldmatrix / cp.async
// ---------------------------------------------------------------------------
__device__ __forceinline__ uint32_t smem_u32(const void* p) {
    uint32_t a;
    asm("{ .reg .u64 t; cvta.to.shared.u64 t, %1; cvt.u32.u64 %0, t; }"
        : "=r"(a) : "l"(p));
    return a;
}
__device__ __forceinline__ void cpa16(uint32_t dst, const void* src) {
    asm volatile("cp.async.cg.shared.global [%0], [%1], 16;"
                 :: "r"(dst), "l"(src));
}
#define CP_COMMIT() asm volatile("cp.async.commit_group;" ::: "memory")
#define CP_WAIT(n)  asm volatile("cp.async.wait_group %0;" :: "n"(n) : "memory")

__device__ __forceinline__ void ldsm4(uint32_t* r, uint32_t addr) {
    asm volatile("ldmatrix.sync.aligned.m8n8.x4.shared.b16 {%0,%1,%2,%3}, [%4];"
                 : "=r"(r[0]), "=r"(r[1]), "=r"(r[2]), "=r"(r[3]) : "r"(addr));
}
__device__ __forceinline__ void mma_bf16(float* d, const uint32_t* a,
                                         const uint32_t* b) {
    asm volatile("mma.sync.aligned.m16n8k16.row.col.f32.bf16.bf16.f32 "
                 "{%0,%1,%2,%3}, {%4,%5,%6,%7}, {%8,%9}, {%0,%1,%2,%3};"
                 : "+f"(d[0]), "+f"(d[1]), "+f"(d[2]), "+f"(d[3])
                 : "r"(a[0]), "r"(a[1]), "r"(a[2]), "r"(a[3]),
                   "r"(b[0]), "r"(b[1]));
}

// ---------------------------------------------------------------------------
// Weight pre-split: W[K,N] fp32 -> Wh,Wl [N,K] bf16 (transposed, hi/lo split)
// ---------------------------------------------------------------------------
__global__ void conv_w_kernel(const float* __restrict__ W,
                              __nv_bfloat16* __restrict__ Wh,
                              __nv_bfloat16* __restrict__ Wl, int K, int N)
{
    __shared__ float t[32][33];
    const int n0 = blockIdx.x * 32, k0 = blockIdx.y * 32;
    const int tx = threadIdx.x, ty = threadIdx.y;
    #pragma unroll
    for (int i = 0; i < 32; i += 8)
        t[ty + i][tx] = W[(size_t)(k0 + ty + i) * N + n0 + tx];
    __syncthreads();
    #pragma unroll
    for (int i = 0; i < 32; i += 8) {
        int n = ty + i;
        float v = t[tx][n];
        __nv_bfloat16 h = __float2bfloat16(v);
        __nv_bfloat16 l = __float2bfloat16(v - __bfloat162float(h));
        size_t o = (size_t)(n0 + n) * K + k0 + tx;
        Wh[o] = h;
        Wl[o] = l;
    }
}

// ---------------------------------------------------------------------------
// Activation pre-split: X fp32 [M,K] -> Xh, Xl bf16 [M,K]
// ---------------------------------------------------------------------------
__global__ void conv_a_kernel(const float* __restrict__ X,
                              __nv_bfloat16* __restrict__ Xh,
                              __nv_bfloat16* __restrict__ Xl, int n4)
{
    int idx = blockIdx.x * blockDim.x + threadIdx.x;
    if (idx >= n4) return;
    float4 v = ((const float4*)X)[idx];
    __nv_bfloat162 h0, h1, l0, l1;
    h0.x = __float2bfloat16(v.x); h0.y = __float2bfloat16(v.y);
    h1.x = __float2bfloat16(v.z); h1.y = __float2bfloat16(v.w);
    l0.x = __float2bfloat16(v.x - __bfloat162float(h0.x));
    l0.y = __float2bfloat16(v.y - __bfloat162float(h0.y));
    l1.x = __float2bfloat16(v.z - __bfloat162float(h1.x));
    l1.y = __float2bfloat16(v.w - __bfloat162float(h1.y));
    ((__nv_bfloat162*)Xh)[idx * 2 + 0] = h0;
    ((__nv_bfloat162*)Xh)[idx * 2 + 1] = h1;
    ((__nv_bfloat162*)Xl)[idx * 2 + 0] = l0;
    ((__nv_bfloat162*)Xl)[idx * 2 + 1] = l1;
}

// ---------------------------------------------------------------------------
// Tensor-core GEMM via mma.sync (bf16 3-term split, fp32 accumulate):
//   C[M,N] = Ah@Bh + Ah@Bl + Al@Bh + bias
// A (split) [M,K] row-major, B (split) [N,K] row-major (i.e. B^T K-major).
// Block 128x128, BK=32, 8 warps (2x4), warp tile 64x32, 2-stage cp.async.
// ---------------------------------------------------------------------------
#define GBK 32
#define AROW 40                 // smem row stride in bf16 (80 B)
#define MAT_BYTES (128 * AROW * 2)    // 10240
#define ST_A_H 0
#define ST_A_L (1 * MAT_BYTES)
#define ST_B_H (2 * MAT_BYTES)
#define ST_B_L (3 * MAT_BYTES)
#define STAGE_B (4 * MAT_BYTES)       // 40960
#define GEMM_SMEM (2 * STAGE_B)       // 81920

__device__ __forceinline__ void gemm_load_chunk(
    uint32_t stBase,
    const __nv_bfloat16* __restrict__ Ah, const __nv_bfloat16* __restrict__ Al,
    const __nv_bfloat16* __restrict__ Bh, const __nv_bfloat16* __restrict__ Bl,
    int bm0, int bn0, int k0, int K, int tid)
{
    const int row = tid >> 1;             // 0..127 (A row / B n-row)
    const int kc  = (tid & 1) * 16;       // 0 or 16
    const size_t ga = (size_t)(bm0 + row) * K + k0 + kc;
    const size_t gb = (size_t)(bn0 + row) * K + k0 + kc;
    const uint32_t so = (uint32_t)(row * 80 + kc * 2);
    cpa16(stBase + ST_A_H + so,      Ah + ga);
    cpa16(stBase + ST_A_H + so + 16, Ah + ga + 8);
    cpa16(stBase + ST_A_L + so,      Al + ga);
    cpa16(stBase + ST_A_L + so + 16, Al + ga + 8);
    cpa16(stBase + ST_B_H + so,      Bh + gb);
    cpa16(stBase + ST_B_H + so + 16, Bh + gb + 8);
    cpa16(stBase + ST_B_L + so,      Bl + gb);
    cpa16(stBase + ST_B_L + so + 16, Bl + gb + 8);
}

__global__ __launch_bounds__(256)
void gemm_tc_kernel(const __nv_bfloat16* __restrict__ Ah,
                    const __nv_bfloat16* __restrict__ Al,
                    const __nv_bfloat16* __restrict__ Bh,
                    const __nv_bfloat16* __restrict__ Bl,
                    const float* __restrict__ bias, float* __restrict__ C,
                    int M, int N, int K)
{
    extern __shared__ char smraw[];
    const uint32_t sb = smem_u32(smraw);
    const int tid = threadIdx.x, wid = tid >> 5, lane = tid & 31;
    const int bm0 = blockIdx.y * 128, bn0 = blockIdx.x * 128;
    const int wm = wid >> 2, wn = wid & 3;       // warp tile: 64x32

    // ldmatrix per-lane address components
    const int a_r = (lane & 7) + ((lane >> 3) & 1) * 8;
    const int a_k = (lane >> 4) * 8;
    const int b_r = (lane & 7) + (lane >> 4) * 8;
    const int b_k = ((lane >> 3) & 1) * 8;

    float acc[4][4][4];
    #pragma unroll
    for (int i = 0; i < 4; i++)
        #pragma unroll
        for (int j = 0; j < 4; j++)
            #pragma unroll
            for (int v = 0; v < 4; v++) acc[i][j][v] = 0.0f;

    const int NCH = K / GBK;

    gemm_load_chunk(sb, Ah, Al, Bh, Bl, bm0, bn0, 0, K, tid);
    CP_COMMIT();

    for (int c = 0; c < NCH; c++) {
        const uint32_t st = sb + (uint32_t)(c & 1) * STAGE_B;
        if (c + 1 < NCH) {
            gemm_load_chunk(sb + (uint32_t)((c + 1) & 1) * STAGE_B,
                            Ah, Al, Bh, Bl, bm0, bn0, (c + 1) * GBK, K, tid);
            CP_COMMIT();
            CP_WAIT(1);
        } else {
            CP_WAIT(0);
        }
        __syncthreads();

        #pragma unroll
        for (int ks = 0; ks < 2; ks++) {
            const int k0 = ks * 16;
            // B fragments: 4 n8-frags (hi and lo)
            uint32_t bh[4][2], bl[4][2];
            #pragma unroll
            for (int half = 0; half < 2; half++) {
                uint32_t baddr = (uint32_t)((wn * 32 + half * 16 + b_r) * 80
                                            + (k0 + b_k) * 2);
                uint32_t r[4];
                ldsm4(r, st + ST_B_H + baddr);
                bh[half * 2 + 0][0] = r[0]; bh[half * 2 + 0][1] = r[1];
                bh[half * 2 + 1][0] = r[2]; bh[half * 2 + 1][1] = r[3];
                ldsm4(r, st + ST_B_L + baddr);
                bl[half * 2 + 0][0] = r[0]; bl[half * 2 + 0][1] = r[1];
                bl[half * 2 + 1][0] = r[2]; bl[half * 2 + 1][1] = r[3];
            }
            #pragma unroll
            for (int mi = 0; mi < 4; mi++) {
                uint32_t aaddr = (uint32_t)((wm * 64 + mi * 16 + a_r) * 80
                                            + (k0 + a_k) * 2);
                uint32_t ah[4], al[4];
                ldsm4(ah, st + ST_A_H + aaddr);
                ldsm4(al, st + ST_A_L + aaddr);
                #pragma unroll
                for (int nf = 0; nf < 4; nf++) {
                    mma_bf16(acc[mi][nf], ah, bh[nf]);
                    mma_bf16(acc[mi][nf], ah, bl[nf]);
                    mma_bf16(acc[mi][nf], al, bh[nf]);
                }
            }
        }
        __syncthreads();
    }

    // Epilogue: fragment -> gmem with bias
    #pragma unroll
    for (int mi = 0; mi < 4; mi++) {
        const int row = bm0 + wm * 64 + mi * 16 + (lane >> 2);
        #pragma unroll
        for (int nf = 0; nf < 4; nf++) {
            const int col = bn0 + wn * 32 + nf * 8 + (lane & 3) * 2;
            const float b0 = bias[col], b1 = bias[col + 1];
            float2 v0, v1;
            v0.x = acc[mi][nf][0] + b0; v0.y = acc[mi][nf][1] + b1;
            v1.x = acc[mi][nf][2] + b0; v1.y = acc[mi][nf][3] + b1;
            *(float2*)&C[(size_t)row * N + col]       = v0;
            *(float2*)&C[(size_t)(row + 8) * N + col] = v1;
        }
    }
}

// ---------------------------------------------------------------------------
// Flash attention (fp32, non-causal, key mask) — unchanged (R1-passing)
// ---------------------------------------------------------------------------
#define ATTN_SMEM_BYTES ((64*64 + 64*65 + 64*64 + 64*64) * 4 + 64 * 4)

__global__ __launch_bounds__(256)
void attn_kernel(const float* __restrict__ qkv, const int* __restrict__ mask,
                 float* __restrict__ out)
{
    extern __shared__ float smf[];
    float* Qs = smf;
    float* Ks = Qs + 64 * 64;
    float* Vs = Ks + 64 * 65;
    float* Ps = Vs + 64 * 64;
    int*  msk = (int*)(Ps + 64 * 64);

    const int tid  = threadIdx.x;
    const int lane = tid & 31;
    const int wid  = tid >> 5;
    const int bh = blockIdx.y;
    const int b  = bh >> 4;
    const int h  = bh & 15;
    const int t0 = blockIdx.x * 64;

    const int mrow0 = wid * 8 + (lane >> 4) * 4;
    const int nc0   = (lane & 15) * 4;

    const size_t base = (size_t)b * TT * N_QKV + (size_t)h * DH;

    #pragma unroll
    for (int i = 0; i < 4; i++) {
        int f = tid + i * 256;
        int m = f >> 4;
        int d4 = (f & 15) * 4;
        *(float4*)&Qs[m * 64 + d4] =
            *(const float4*)&qkv[base + (size_t)(t0 + m) * N_QKV + d4];
    }

    float m_i[4], l_i[4], o[4][4];
    #pragma unroll
    for (int i = 0; i < 4; i++) {
        m_i[i] = -3.0e38f;
        l_i[i] = 0.0f;
        #pragma unroll
        for (int j = 0; j < 4; j++) o[i][j] = 0.0f;
    }

    for (int n0 = 0; n0 < TT; n0 += 64) {
        __syncthreads();

        #pragma unroll
        for (int i = 0; i < 4; i++) {
            int f = tid + i * 256;
            int m = f >> 4;
            int d4 = (f & 15) * 4;
            float4 kv = *(const float4*)&qkv[base + DD + (size_t)(n0 + m) * N_QKV + d4];
            Ks[m * 65 + d4 + 0] = kv.x;
            Ks[m * 65 + d4 + 1] = kv.y;
            Ks[m * 65 + d4 + 2] = kv.z;
            Ks[m * 65 + d4 + 3] = kv.w;
            *(float4*)&Vs[m * 64 + d4] =
                *(const float4*)&qkv[base + 2 * DD + (size_t)(n0 + m) * N_QKV + d4];
        }
        if (tid < 64) msk[tid] = mask[b * TT + n0 + tid];
        __syncthreads();

        float acc[4][4];
        #pragma unroll
        for (int i = 0; i < 4; i++)
            #pragma unroll
            for (int j = 0; j < 4; j++) acc[i][j] = 0.0f;

        #pragma unroll 8
        for (int d = 0; d < DH; d++) {
            float a[4], bb[4];
            #pragma unroll
            for (int i = 0; i < 4; i++) a[i]  = Qs[(mrow0 + i) * 64 + d];
            #pragma unroll
            for (int j = 0; j < 4; j++) bb[j] = Ks[(nc0 + j) * 65 + d];
            #pragma unroll
            for (int i = 0; i < 4; i++)
                #pragma unroll
                for (int j = 0; j < 4; j++)
                    acc[i][j] += a[i] * bb[j];
        }

        int mk[4];
        #pragma unroll
        for (int j = 0; j < 4; j++) mk[j] = msk[nc0 + j];

        #pragma unroll
        for (int i = 0; i < 4; i++) {
            float tm = -3.0e38f;
            #pragma unroll
            for (int j = 0; j < 4; j++) {
                float s = mk[j] ? acc[i][j] * 0.125f : -1000.0f;
                acc[i][j] = s;
                tm = fmaxf(tm, s);
            }
            #pragma unroll
            for (int off = 1; off < 16; off <<= 1)
                tm = fmaxf(tm, __shfl_xor_sync(0xffffffffu, tm, off));

            float mn = fmaxf(m_i[i], tm);
            float alpha = __expf(m_i[i] - mn);
            m_i[i] = mn;

            float p0 = __expf(acc[i][0] - mn);
            float p1 = __expf(acc[i][1] - mn);
            float p2 = __expf(acc[i][2] - mn);
            float p3 = __expf(acc[i][3] - mn);
            float rs = p0 + p1 + p2 + p3;
            #pragma unroll
            for (int off = 1; off < 16; off <<= 1)
                rs += __shfl_xor_sync(0xffffffffu, rs, off);

            l_i[i] = l_i[i] * alpha + rs;
            #pragma unroll
            for (int j = 0; j < 4; j++) o[i][j] *= alpha;

            float4 pv; pv.x = p0; pv.y = p1; pv.z = p2; pv.w = p3;
            *(float4*)&Ps[(mrow0 + i) * 64 + nc0] = pv;
        }
        __syncthreads();

        #pragma unroll 8
        for (int n = 0; n < 64; n++) {
            float a[4];
            #pragma unroll
            for (int i = 0; i < 4; i++) a[i] = Ps[(mrow0 + i) * 64 + n];
            float4 v = *(const float4*)&Vs[n * 64 + nc0];
            #pragma unroll
            for (int i = 0; i < 4; i++) {
                o[i][0] += a[i] * v.x;
                o[i][1] += a[i] * v.y;
                o[i][2] += a[i] * v.z;
                o[i][3] += a[i] * v.w;
            }
        }
    }

    #pragma unroll
    for (int i = 0; i < 4; i++) {
        float inv = 1.0f / l_i[i];
        float4 ov;
        ov.x = o[i][0] * inv; ov.y = o[i][1] * inv;
        ov.z = o[i][2] * inv; ov.w = o[i][3] * inv;
        size_t off = (size_t)(b * TT + t0 + mrow0 + i) * DD + h * DH + nc0;
        *(float4*)&out[off] = ov;
    }
}

// ---------------------------------------------------------------------------
extern "C" void kernel_launch(void* const* d_in, const int* in_sizes, int n_in,
                              void* d_out, int out_size)
{
    const float* x     = (const float*)d_in[0];
    const int*   mask  = (const int*)  d_in[1];
    const float* W_qkv = (const float*)d_in[2];
    const float* b_qkv = (const float*)d_in[3];
    const float* W_out = (const float*)d_in[4];
    const float* b_out = (const float*)d_in[5];
    float* out = (float*)d_out;

    float* qkv  = nullptr;
    float* attn = nullptr;
    __nv_bfloat16 *wqh, *wql, *woh, *wol, *xh, *xl;
    cudaGetSymbolAddress((void**)&qkv,  g_qkv);
    cudaGetSymbolAddress((void**)&attn, g_attn);
    cudaGetSymbolAddress((void**)&wqh, g_wqkv_h);
    cudaGetSymbolAddress((void**)&wql, g_wqkv_l);
    cudaGetSymbolAddress((void**)&woh, g_wout_h);
    cudaGetSymbolAddress((void**)&wol, g_wout_l);
    cudaGetSymbolAddress((void**)&xh,  g_act_h);
    cudaGetSymbolAddress((void**)&xl,  g_act_l);

    cudaFuncSetAttribute(attn_kernel,
                         cudaFuncAttributeMaxDynamicSharedMemorySize,
                         ATTN_SMEM_BYTES);
    cudaFuncSetAttribute(gemm_tc_kernel,
                         cudaFuncAttributeMaxDynamicSharedMemorySize,
                         GEMM_SMEM);

    const int n4 = MTOT * DD / 4;

    // 0) Pre-split weights (transposed [N,K]) and input activations
    conv_w_kernel<<<dim3(N_QKV / 32, DD / 32), dim3(32, 8)>>>(W_qkv, wqh, wql, DD, N_QKV);
    conv_w_kernel<<<dim3(DD / 32, DD / 32),   dim3(32, 8)>>>(W_out, woh, wol, DD, DD);
    conv_a_kernel<<<(n4 + 255) / 256, 256>>>(x, xh, xl, n4);

    // 1) QKV projection (mma.sync bf16 split)
    gemm_tc_kernel<<<dim3(N_QKV / 128, MTOT / 128), 256, GEMM_SMEM>>>(
        xh, xl, wqh, wql, b_qkv, qkv, MTOT, N_QKV, DD);

    // 2) Attention
    attn_kernel<<<dim3(TT / 64, BB * HH), 256, ATTN_SMEM_BYTES>>>(qkv, mask, attn);

    // 3) Split attention output, then output projection
    conv_a_kernel<<<(n4 + 255) / 256, 256>>>(attn, xh, xl, n4);
    gemm_tc_kernel<<<dim3(DD / 128, MTOT / 128), 256, GEMM_SMEM>>>(
        xh, xl, woh, wol, b_out, out, MTOT, DD, DD);
}

// round 5
// speedup vs baseline: 2.2848x; 1.7044x over previous
#include <cuda_runtime.h>
#include <cuda_bf16.h>
#include <cstdint>
#include <math.h>

// Problem constants
#define BB 4
#define TT 2048
#define DD 1024
#define HH 16
#define DH 64
#define MTOT (BB*TT)        // 8192
#define N_QKV (3*DD)        // 3072

// Scratch (device globals: allocation-guard safe)
__device__ __nv_bfloat16 g_wqkv_h[(size_t)N_QKV * DD];  // W_qkv^T hi  [3072,1024]
__device__ __nv_bfloat16 g_wqkv_l[(size_t)N_QKV * DD];
__device__ __nv_bfloat16 g_wout_h[(size_t)DD * DD];     // W_out^T hi  [1024,1024]
__device__ __nv_bfloat16 g_wout_l[(size_t)DD * DD];
__device__ __nv_bfloat16 g_act_h[(size_t)MTOT * DD];    // activation hi [M,K]
__device__ __nv_bfloat16 g_act_l[(size_t)MTOT * DD];
// Q/K/V head-major [B*H][T][DH], hi/lo split (Q pre-scaled by 0.125)
#define QKV_ELEMS ((size_t)BB * HH * TT * DH)
__device__ __nv_bfloat16 g_q_h[QKV_ELEMS];
__device__ __nv_bfloat16 g_q_l[QKV_ELEMS];
__device__ __nv_bfloat16 g_k_h[QKV_ELEMS];
__device__ __nv_bfloat16 g_k_l[QKV_ELEMS];
__device__ __nv_bfloat16 g_v_h[QKV_ELEMS];
__device__ __nv_bfloat16 g_v_l[QKV_ELEMS];

// ---------------------------------------------------------------------------
// sm_80-portable PTX helpers
// ---------------------------------------------------------------------------
__device__ __forceinline__ uint32_t smem_u32(const void* p) {
    uint32_t a;
    asm("{ .reg .u64 t; cvta.to.shared.u64 t, %1; cvt.u32.u64 %0, t; }"
        : "=r"(a) : "l"(p));
    return a;
}
__device__ __forceinline__ void cpa16(uint32_t dst, const void* src) {
    asm volatile("cp.async.cg.shared.global [%0], [%1], 16;"
                 :: "r"(dst), "l"(src));
}
__device__ __forceinline__ void cpa4(uint32_t dst, const void* src) {
    asm volatile("cp.async.ca.shared.global [%0], [%1], 4;"
                 :: "r"(dst), "l"(src));
}
#define CP_COMMIT() asm volatile("cp.async.commit_group;" ::: "memory")
#define CP_WAIT(n)  asm volatile("cp.async.wait_group %0;" :: "n"(n) : "memory")

__device__ __forceinline__ void ldsm4(uint32_t* r, uint32_t addr) {
    asm volatile("ldmatrix.sync.aligned.m8n8.x4.shared.b16 {%0,%1,%2,%3}, [%4];"
                 : "=r"(r[0]), "=r"(r[1]), "=r"(r[2]), "=r"(r[3]) : "r"(addr));
}
__device__ __forceinline__ void ldsm4t(uint32_t* r, uint32_t addr) {
    asm volatile("ldmatrix.sync.aligned.m8n8.x4.trans.shared.b16 {%0,%1,%2,%3}, [%4];"
                 : "=r"(r[0]), "=r"(r[1]), "=r"(r[2]), "=r"(r[3]) : "r"(addr));
}
__device__ __forceinline__ void mma_bf16(float* d, const uint32_t* a,
                                         const uint32_t* b) {
    asm volatile("mma.sync.aligned.m16n8k16.row.col.f32.bf16.bf16.f32 "
                 "{%0,%1,%2,%3}, {%4,%5,%6,%7}, {%8,%9}, {%0,%1,%2,%3};"
                 : "+f"(d[0]), "+f"(d[1]), "+f"(d[2]), "+f"(d[3])
                 : "r"(a[0]), "r"(a[1]), "r"(a[2]), "r"(a[3]),
                   "r"(b[0]), "r"(b[1]));
}
// split pair of fp32 -> bf16x2 hi + bf16x2 lo
__device__ __forceinline__ void split2(float x, float y, uint32_t& hi, uint32_t& lo) {
    __nv_bfloat162 h, l;
    h.x = __float2bfloat16(x);
    h.y = __float2bfloat16(y);
    l.x = __float2bfloat16(x - __bfloat162float(h.x));
    l.y = __float2bfloat16(y - __bfloat162float(h.y));
    hi = *(uint32_t*)&h;
    lo = *(uint32_t*)&l;
}

// ---------------------------------------------------------------------------
// Weight pre-split: W[K,N] fp32 -> Wh,Wl [N,K] bf16 (transposed, hi/lo split)
// ---------------------------------------------------------------------------
__global__ void conv_w_kernel(const float* __restrict__ W,
                              __nv_bfloat16* __restrict__ Wh,
                              __nv_bfloat16* __restrict__ Wl, int K, int N)
{
    __shared__ float t[32][33];
    const int n0 = blockIdx.x * 32, k0 = blockIdx.y * 32;
    const int tx = threadIdx.x, ty = threadIdx.y;
    #pragma unroll
    for (int i = 0; i < 32; i += 8)
        t[ty + i][tx] = W[(size_t)(k0 + ty + i) * N + n0 + tx];
    __syncthreads();
    #pragma unroll
    for (int i = 0; i < 32; i += 8) {
        int n = ty + i;
        float v = t[tx][n];
        __nv_bfloat16 h = __float2bfloat16(v);
        __nv_bfloat16 l = __float2bfloat16(v - __bfloat162float(h));
        size_t o = (size_t)(n0 + n) * K + k0 + tx;
        Wh[o] = h;
        Wl[o] = l;
    }
}

// ---------------------------------------------------------------------------
// Activation pre-split: X fp32 [M,K] -> Xh, Xl bf16 [M,K]
// ---------------------------------------------------------------------------
__global__ void conv_a_kernel(const float* __restrict__ X,
                              __nv_bfloat16* __restrict__ Xh,
                              __nv_bfloat16* __restrict__ Xl, int n4)
{
    int idx = blockIdx.x * blockDim.x + threadIdx.x;
    if (idx >= n4) return;
    float4 v = ((const float4*)X)[idx];
    uint32_t h0, h1, l0, l1;
    split2(v.x, v.y, h0, l0);
    split2(v.z, v.w, h1, l1);
    ((uint32_t*)Xh)[idx * 2 + 0] = h0;
    ((uint32_t*)Xh)[idx * 2 + 1] = h1;
    ((uint32_t*)Xl)[idx * 2 + 0] = l0;
    ((uint32_t*)Xl)[idx * 2 + 1] = l1;
}

// ---------------------------------------------------------------------------
// Tensor-core GEMM via mma.sync (bf16 3-term split, fp32 accumulate)
// Two epilogues: plain C+bias (qh==nullptr), or QKV scatter-split.
// ---------------------------------------------------------------------------
#define GBK 32
#define AROW 40
#define MAT_BYTES (128 * AROW * 2)
#define ST_A_H 0
#define ST_A_L (1 * MAT_BYTES)
#define ST_B_H (2 * MAT_BYTES)
#define ST_B_L (3 * MAT_BYTES)
#define STAGE_B (4 * MAT_BYTES)
#define GEMM_SMEM (2 * STAGE_B)

__device__ __forceinline__ void gemm_load_chunk(
    uint32_t stBase,
    const __nv_bfloat16* __restrict__ Ah, const __nv_bfloat16* __restrict__ Al,
    const __nv_bfloat16* __restrict__ Bh, const __nv_bfloat16* __restrict__ Bl,
    int bm0, int bn0, int k0, int K, int tid)
{
    const int row = tid >> 1;
    const int kc  = (tid & 1) * 16;
    const size_t ga = (size_t)(bm0 + row) * K + k0 + kc;
    const size_t gb = (size_t)(bn0 + row) * K + k0 + kc;
    const uint32_t so = (uint32_t)(row * 80 + kc * 2);
    cpa16(stBase + ST_A_H + so,      Ah + ga);
    cpa16(stBase + ST_A_H + so + 16, Ah + ga + 8);
    cpa16(stBase + ST_A_L + so,      Al + ga);
    cpa16(stBase + ST_A_L + so + 16, Al + ga + 8);
    cpa16(stBase + ST_B_H + so,      Bh + gb);
    cpa16(stBase + ST_B_H + so + 16, Bh + gb + 8);
    cpa16(stBase + ST_B_L + so,      Bl + gb);
    cpa16(stBase + ST_B_L + so + 16, Bl + gb + 8);
}

__global__ __launch_bounds__(256)
void gemm_tc_kernel(const __nv_bfloat16* __restrict__ Ah,
                    const __nv_bfloat16* __restrict__ Al,
                    const __nv_bfloat16* __restrict__ Bh,
                    const __nv_bfloat16* __restrict__ Bl,
                    const float* __restrict__ bias, float* __restrict__ C,
                    int M, int N, int K,
                    __nv_bfloat16* qh, __nv_bfloat16* ql,
                    __nv_bfloat16* kh, __nv_bfloat16* kl,
                    __nv_bfloat16* vh, __nv_bfloat16* vl)
{
    extern __shared__ char smraw[];
    const uint32_t sb = smem_u32(smraw);
    const int tid = threadIdx.x, wid = tid >> 5, lane = tid & 31;
    const int bm0 = blockIdx.y * 128, bn0 = blockIdx.x * 128;
    const int wm = wid >> 2, wn = wid & 3;

    const int a_r = (lane & 7) + ((lane >> 3) & 1) * 8;
    const int a_k = (lane >> 4) * 8;
    const int b_r = (lane & 7) + (lane >> 4) * 8;
    const int b_k = ((lane >> 3) & 1) * 8;

    float acc[4][4][4];
    #pragma unroll
    for (int i = 0; i < 4; i++)
        #pragma unroll
        for (int j = 0; j < 4; j++)
            #pragma unroll
            for (int v = 0; v < 4; v++) acc[i][j][v] = 0.0f;

    const int NCH = K / GBK;

    gemm_load_chunk(sb, Ah, Al, Bh, Bl, bm0, bn0, 0, K, tid);
    CP_COMMIT();

    for (int c = 0; c < NCH; c++) {
        const uint32_t st = sb + (uint32_t)(c & 1) * STAGE_B;
        if (c + 1 < NCH) {
            gemm_load_chunk(sb + (uint32_t)((c + 1) & 1) * STAGE_B,
                            Ah, Al, Bh, Bl, bm0, bn0, (c + 1) * GBK, K, tid);
            CP_COMMIT();
            CP_WAIT(1);
        } else {
            CP_WAIT(0);
        }
        __syncthreads();

        #pragma unroll
        for (int ks = 0; ks < 2; ks++) {
            const int k0 = ks * 16;
            uint32_t bh2[4][2], bl2[4][2];
            #pragma unroll
            for (int half = 0; half < 2; half++) {
                uint32_t baddr = (uint32_t)((wn * 32 + half * 16 + b_r) * 80
                                            + (k0 + b_k) * 2);
                uint32_t r[4];
                ldsm4(r, st + ST_B_H + baddr);
                bh2[half * 2 + 0][0] = r[0]; bh2[half * 2 + 0][1] = r[1];
                bh2[half * 2 + 1][0] = r[2]; bh2[half * 2 + 1][1] = r[3];
                ldsm4(r, st + ST_B_L + baddr);
                bl2[half * 2 + 0][0] = r[0]; bl2[half * 2 + 0][1] = r[1];
                bl2[half * 2 + 1][0] = r[2]; bl2[half * 2 + 1][1] = r[3];
            }
            #pragma unroll
            for (int mi = 0; mi < 4; mi++) {
                uint32_t aaddr = (uint32_t)((wm * 64 + mi * 16 + a_r) * 80
                                            + (k0 + a_k) * 2);
                uint32_t ah[4], al[4];
                ldsm4(ah, st + ST_A_H + aaddr);
                ldsm4(al, st + ST_A_L + aaddr);
                #pragma unroll
                for (int nf = 0; nf < 4; nf++) {
                    mma_bf16(acc[mi][nf], ah, bh2[nf]);
                    mma_bf16(acc[mi][nf], ah, bl2[nf]);
                    mma_bf16(acc[mi][nf], al, bh2[nf]);
                }
            }
        }
        __syncthreads();
    }

    // Epilogue
    #pragma unroll
    for (int mi = 0; mi < 4; mi++) {
        const int row = bm0 + wm * 64 + mi * 16 + (lane >> 2);
        #pragma unroll
        for (int nf = 0; nf < 4; nf++) {
            const int col = bn0 + wn * 32 + nf * 8 + (lane & 3) * 2;
            const float b0 = bias[col], b1 = bias[col + 1];
            float v0 = acc[mi][nf][0] + b0, v1 = acc[mi][nf][1] + b1;
            float v2 = acc[mi][nf][2] + b0, v3 = acc[mi][nf][3] + b1;
            if (qh == nullptr) {
                float2 p0, p1;
                p0.x = v0; p0.y = v1; p1.x = v2; p1.y = v3;
                *(float2*)&C[(size_t)row * N + col]       = p0;
                *(float2*)&C[(size_t)(row + 8) * N + col] = p1;
            } else {
                // scatter to head-major split QKV
                const int sec = col >> 10;
                const int hh  = (col >> 6) & 15;
                const int d   = col & 63;
                const int bb  = row >> 11;
                const int trow = row & 2047;
                const float sc = (sec == 0) ? 0.125f : 1.0f;
                __nv_bfloat16 *H, *L;
                if (sec == 0)      { H = qh; L = ql; }
                else if (sec == 1) { H = kh; L = kl; }
                else               { H = vh; L = vl; }
                size_t dst = (((size_t)(bb * 16 + hh)) * TT + trow) * 64 + d;
                uint32_t hi, lo;
                split2(v0 * sc, v1 * sc, hi, lo);
                *(uint32_t*)(H + dst) = hi;
                *(uint32_t*)(L + dst) = lo;
                split2(v2 * sc, v3 * sc, hi, lo);
                *(uint32_t*)(H + dst + 8 * 64) = hi;
                *(uint32_t*)(L + dst + 8 * 64) = lo;
            }
        }
    }
}

// ---------------------------------------------------------------------------
// Tensor-core flash attention (bf16 3-term split, fp32 softmax):
//   BM=128 (8 warps x 16 rows), BN=64, DH=64, double-buffered K/V.
//   Q pre-scaled by 1/8. Writes output pre-split bf16 hi/lo (GEMM2 A).
// ---------------------------------------------------------------------------
#define AVROW 72                       // bf16 row stride (144 B)
#define AQH 0
#define AQL (128 * AVROW * 2)          // 18432
#define AST (2 * 128 * AVROW * 2)      // 36864
#define AKH 0
#define AKL (64 * AVROW * 2)           // 9216
#define AVH (2 * 64 * AVROW * 2)
#define AVL (3 * 64 * AVROW * 2)
#define ASTAGE (4 * 64 * AVROW * 2)    // 36864
#define AMSK (AST + 2 * ASTAGE)        // 110592
#define ATTN_SMEM (AMSK + 512)

__device__ __forceinline__ void attn_kvload(
    uint32_t sb, int stage, int bh, int n0,
    const __nv_bfloat16* __restrict__ Kh_g, const __nv_bfloat16* __restrict__ Kl_g,
    const __nv_bfloat16* __restrict__ Vh_g, const __nv_bfloat16* __restrict__ Vl_g,
    const int* __restrict__ mask, int b, int tid)
{
    const uint32_t st = sb + AST + (uint32_t)stage * ASTAGE;
    const size_t gb = ((size_t)bh * TT + n0) * 64;
    #pragma unroll
    for (int u = 0; u < 2; u++) {
        int idx = tid * 2 + u;
        int row = idx >> 3, ch = idx & 7;
        uint32_t so = (uint32_t)(row * 144 + ch * 16);
        size_t go = gb + row * 64 + ch * 8;
        cpa16(st + AKH + so, Kh_g + go);
        cpa16(st + AKL + so, Kl_g + go);
        cpa16(st + AVH + so, Vh_g + go);
        cpa16(st + AVL + so, Vl_g + go);
    }
    if (tid < 64)
        cpa4(sb + AMSK + (uint32_t)stage * 256 + tid * 4,
             mask + (size_t)b * TT + n0 + tid);
}

__global__ __launch_bounds__(256)
void attn_tc_kernel(const __nv_bfloat16* __restrict__ Qh_g,
                    const __nv_bfloat16* __restrict__ Ql_g,
                    const __nv_bfloat16* __restrict__ Kh_g,
                    const __nv_bfloat16* __restrict__ Kl_g,
                    const __nv_bfloat16* __restrict__ Vh_g,
                    const __nv_bfloat16* __restrict__ Vl_g,
                    const int* __restrict__ mask,
                    __nv_bfloat16* __restrict__ Oh_g,
                    __nv_bfloat16* __restrict__ Ol_g)
{
    extern __shared__ char smraw[];
    const uint32_t sb = smem_u32(smraw);
    const int tid = threadIdx.x, wid = tid >> 5, lane = tid & 31;
    const int bh = blockIdx.y;
    const int b = bh >> 4, h = bh & 15;
    const int t0 = blockIdx.x * 128;
    const int wm = wid;   // warp rows: wm*16 .. wm*16+15

    const int a_r = (lane & 7) + ((lane >> 3) & 1) * 8;
    const int a_k = (lane >> 4) * 8;
    const int b_r = (lane & 7) + (lane >> 4) * 8;
    const int b_k = ((lane >> 3) & 1) * 8;
    const int c0base = (lane & 3) * 2;

    // --- Q tile load (128 rows x 64) + KV tile 0 ---
    const size_t qbase = ((size_t)bh * TT + t0) * 64;
    #pragma unroll
    for (int i = 0; i < 4; i++) {
        int f = tid + i * 256;
        int row = f >> 3, ch = f & 7;
        uint32_t so = (uint32_t)(row * 144 + ch * 16);
        size_t go = qbase + row * 64 + ch * 8;
        cpa16(sb + AQH + so, Qh_g + go);
        cpa16(sb + AQL + so, Ql_g + go);
    }
    attn_kvload(sb, 0, bh, 0, Kh_g, Kl_g, Vh_g, Vl_g, mask, b, tid);
    CP_COMMIT();
    CP_WAIT(0);
    __syncthreads();

    // --- Q fragments to registers (4 k16-steps over DH) ---
    uint32_t qfh[4][4], qfl[4][4];
    #pragma unroll
    for (int kk = 0; kk < 4; kk++) {
        uint32_t addr = (uint32_t)(((wm * 16 + a_r) * AVROW + kk * 16 + a_k) * 2);
        ldsm4(qfh[kk], sb + AQH + addr);
        ldsm4(qfl[kk], sb + AQL + addr);
    }

    float O[8][4];
    #pragma unroll
    for (int j = 0; j < 8; j++)
        #pragma unroll
        for (int v = 0; v < 4; v++) O[j][v] = 0.0f;
    float m0 = -3.0e38f, m1 = -3.0e38f, l0 = 0.0f, l1 = 0.0f;

    for (int t = 0; t < TT / 64; t++) {
        const int s = t & 1;
        if (t + 1 < TT / 64) {
            attn_kvload(sb, s ^ 1, bh, (t + 1) * 64,
                        Kh_g, Kl_g, Vh_g, Vl_g, mask, b, tid);
            CP_COMMIT();
        }
        const uint32_t st = sb + AST + (uint32_t)s * ASTAGE;
        const int* msk = (const int*)(smraw + AMSK + s * 256);

        // --- S = Q K^T (scaled Q), 3-term split ---
        float acc[8][4];
        #pragma unroll
        for (int j = 0; j < 8; j++)
            #pragma unroll
            for (int v = 0; v < 4; v++) acc[j][v] = 0.0f;

        #pragma unroll
        for (int kk = 0; kk < 4; kk++) {
            #pragma unroll
            for (int nb = 0; nb < 4; nb++) {
                uint32_t addr = (uint32_t)(((nb * 16 + b_r) * AVROW
                                            + kk * 16 + b_k) * 2);
                uint32_t rh[4], rl[4];
                ldsm4(rh, st + AKH + addr);
                ldsm4(rl, st + AKL + addr);
                mma_bf16(acc[2 * nb],     qfh[kk], &rh[0]);
                mma_bf16(acc[2 * nb],     qfh[kk], &rl[0]);
                mma_bf16(acc[2 * nb],     qfl[kk], &rh[0]);
                mma_bf16(acc[2 * nb + 1], qfh[kk], &rh[2]);
                mma_bf16(acc[2 * nb + 1], qfh[kk], &rl[2]);
                mma_bf16(acc[2 * nb + 1], qfl[kk], &rh[2]);
            }
        }

        // --- mask + online softmax ---
        float rmax0 = -3.0e38f, rmax1 = -3.0e38f;
        #pragma unroll
        for (int j = 0; j < 8; j++) {
            int c = j * 8 + c0base;
            int mk0 = msk[c], mk1 = msk[c + 1];
            acc[j][0] = mk0 ? acc[j][0] : -1000.0f;
            acc[j][1] = mk1 ? acc[j][1] : -1000.0f;
            acc[j][2] = mk0 ? acc[j][2] : -1000.0f;
            acc[j][3] = mk1 ? acc[j][3] : -1000.0f;
            rmax0 = fmaxf(rmax0, fmaxf(acc[j][0], acc[j][1]));
            rmax1 = fmaxf(rmax1, fmaxf(acc[j][2], acc[j][3]));
        }
        rmax0 = fmaxf(rmax0, __shfl_xor_sync(0xffffffffu, rmax0, 1));
        rmax0 = fmaxf(rmax0, __shfl_xor_sync(0xffffffffu, rmax0, 2));
        rmax1 = fmaxf(rmax1, __shfl_xor_sync(0xffffffffu, rmax1, 1));
        rmax1 = fmaxf(rmax1, __shfl_xor_sync(0xffffffffu, rmax1, 2));

        float mn0 = fmaxf(m0, rmax0), mn1 = fmaxf(m1, rmax1);
        float al0 = __expf(m0 - mn0), al1 = __expf(m1 - mn1);
        m0 = mn0; m1 = mn1;

        float rs0 = 0.0f, rs1 = 0.0f;
        #pragma unroll
        for (int j = 0; j < 8; j++) {
            acc[j][0] = __expf(acc[j][0] - mn0); rs0 += acc[j][0];
            acc[j][1] = __expf(acc[j][1] - mn0); rs0 += acc[j][1];
            acc[j][2] = __expf(acc[j][2] - mn1); rs1 += acc[j][2];
            acc[j][3] = __expf(acc[j][3] - mn1); rs1 += acc[j][3];
        }
        rs0 += __shfl_xor_sync(0xffffffffu, rs0, 1);
        rs0 += __shfl_xor_sync(0xffffffffu, rs0, 2);
        rs1 += __shfl_xor_sync(0xffffffffu, rs1, 1);
        rs1 += __shfl_xor_sync(0xffffffffu, rs1, 2);
        l0 = l0 * al0 + rs0;
        l1 = l1 * al1 + rs1;
        #pragma unroll
        for (int j = 0; j < 8; j++) {
            O[j][0] *= al0; O[j][1] *= al0;
            O[j][2] *= al1; O[j][3] *= al1;
        }

        // --- O += P V (3-term split), V frags via ldmatrix.trans ---
        #pragma unroll
        for (int kk = 0; kk < 4; kk++) {
            uint32_t pah[4], pal[4];
            split2(acc[2 * kk][0],     acc[2 * kk][1],     pah[0], pal[0]);
            split2(acc[2 * kk][2],     acc[2 * kk][3],     pah[1], pal[1]);
            split2(acc[2 * kk + 1][0], acc[2 * kk + 1][1], pah[2], pal[2]);
            split2(acc[2 * kk + 1][2], acc[2 * kk + 1][3], pah[3], pal[3]);
            #pragma unroll
            for (int nb = 0; nb < 4; nb++) {
                uint32_t addr = (uint32_t)(((kk * 16 + ((lane >> 3) & 1) * 8
                                             + (lane & 7)) * AVROW
                                            + nb * 16 + (lane >> 4) * 8) * 2);
                uint32_t vh4[4], vl4[4];
                ldsm4t(vh4, st + AVH + addr);
                ldsm4t(vl4, st + AVL + addr);
                mma_bf16(O[2 * nb],     pah, &vh4[0]);
                mma_bf16(O[2 * nb],     pah, &vl4[0]);
                mma_bf16(O[2 * nb],     pal, &vh4[0]);
                mma_bf16(O[2 * nb + 1], pah, &vh4[2]);
                mma_bf16(O[2 * nb + 1], pah, &vl4[2]);
                mma_bf16(O[2 * nb + 1], pal, &vh4[2]);
            }
        }

        if (t + 1 < TT / 64) CP_WAIT(0);
        __syncthreads();
    }

    // --- normalize + write pre-split output (GEMM2 A layout [M,1024]) ---
    const float inv0 = 1.0f / l0, inv1 = 1.0f / l1;
    const int trow = t0 + wm * 16 + (lane >> 2);
    const size_t ob0 = ((size_t)(b * TT + trow)) * DD + h * 64;
    const size_t ob1 = ob0 + (size_t)8 * DD;
    #pragma unroll
    for (int jn = 0; jn < 8; jn++) {
        int c = jn * 8 + c0base;
        uint32_t hi, lo;
        split2(O[jn][0] * inv0, O[jn][1] * inv0, hi, lo);
        *(uint32_t*)(Oh_g + ob0 + c) = hi;
        *(uint32_t*)(Ol_g + ob0 + c) = lo;
        split2(O[jn][2] * inv1, O[jn][3] * inv1, hi, lo);
        *(uint32_t*)(Oh_g + ob1 + c) = hi;
        *(uint32_t*)(Ol_g + ob1 + c) = lo;
    }
}

// ---------------------------------------------------------------------------
extern "C" void kernel_launch(void* const* d_in, const int* in_sizes, int n_in,
                              void* d_out, int out_size)
{
    const float* x     = (const float*)d_in[0];
    const int*   mask  = (const int*)  d_in[1];
    const float* W_qkv = (const float*)d_in[2];
    const float* b_qkv = (const float*)d_in[3];
    const float* W_out = (const float*)d_in[4];
    const float* b_out = (const float*)d_in[5];
    float* out = (float*)d_out;

    __nv_bfloat16 *wqh, *wql, *woh, *wol, *xh, *xl;
    __nv_bfloat16 *qh, *ql, *kh, *kl, *vh, *vl;
    cudaGetSymbolAddress((void**)&wqh, g_wqkv_h);
    cudaGetSymbolAddress((void**)&wql, g_wqkv_l);
    cudaGetSymbolAddress((void**)&woh, g_wout_h);
    cudaGetSymbolAddress((void**)&wol, g_wout_l);
    cudaGetSymbolAddress((void**)&xh,  g_act_h);
    cudaGetSymbolAddress((void**)&xl,  g_act_l);
    cudaGetSymbolAddress((void**)&qh,  g_q_h);
    cudaGetSymbolAddress((void**)&ql,  g_q_l);
    cudaGetSymbolAddress((void**)&kh,  g_k_h);
    cudaGetSymbolAddress((void**)&kl,  g_k_l);
    cudaGetSymbolAddress((void**)&vh,  g_v_h);
    cudaGetSymbolAddress((void**)&vl,  g_v_l);

    cudaFuncSetAttribute(gemm_tc_kernel,
                         cudaFuncAttributeMaxDynamicSharedMemorySize, GEMM_SMEM);
    cudaFuncSetAttribute(attn_tc_kernel,
                         cudaFuncAttributeMaxDynamicSharedMemorySize, ATTN_SMEM);

    const int n4 = MTOT * DD / 4;

    // 0) Pre-split weights (transposed [N,K]) and input activations
    conv_w_kernel<<<dim3(N_QKV / 32, DD / 32), dim3(32, 8)>>>(W_qkv, wqh, wql, DD, N_QKV);
    conv_w_kernel<<<dim3(DD / 32, DD / 32),   dim3(32, 8)>>>(W_out, woh, wol, DD, DD);
    conv_a_kernel<<<(n4 + 255) / 256, 256>>>(x, xh, xl, n4);

    // 1) QKV projection; epilogue scatters split Q/K/V head-major (Q pre-scaled)
    gemm_tc_kernel<<<dim3(N_QKV / 128, MTOT / 128), 256, GEMM_SMEM>>>(
        xh, xl, wqh, wql, b_qkv, nullptr, MTOT, N_QKV, DD,
        qh, ql, kh, kl, vh, vl);

    // 2) Tensor-core flash attention; writes pre-split activations for GEMM2
    attn_tc_kernel<<<dim3(TT / 128, BB * HH), 256, ATTN_SMEM>>>(
        qh, ql, kh, kl, vh, vl, mask, xh, xl);

    // 3) Output projection
    gemm_tc_kernel<<<dim3(DD / 128, MTOT / 128), 256, GEMM_SMEM>>>(
        xh, xl, woh, wol, b_out, out, MTOT, DD, DD,
        nullptr, nullptr, nullptr, nullptr, nullptr, nullptr);
}

// round 6
// speedup vs baseline: 2.6431x; 1.1568x over previous
#include <cuda_runtime.h>
#include <cuda_bf16.h>
#include <cstdint>
#include <math.h>

// Problem constants
#define BB 4
#define TT 2048
#define DD 1024
#define HH 16
#define DH 64
#define MTOT (BB*TT)        // 8192
#define N_QKV (3*DD)        // 3072

// Scratch (device globals: allocation-guard safe)
__device__ __nv_bfloat16 g_wqkv_h[(size_t)N_QKV * DD];  // W_qkv^T hi  [3072,1024]
__device__ __nv_bfloat16 g_wqkv_l[(size_t)N_QKV * DD];
__device__ __nv_bfloat16 g_wout_h[(size_t)DD * DD];     // W_out^T hi  [1024,1024]
__device__ __nv_bfloat16 g_wout_l[(size_t)DD * DD];
__device__ __nv_bfloat16 g_act_h[(size_t)MTOT * DD];    // activation hi [M,K]
__device__ __nv_bfloat16 g_act_l[(size_t)MTOT * DD];
// Q/K/V head-major [B*H][T][DH], hi/lo split (Q pre-scaled by 0.125)
#define QKV_ELEMS ((size_t)BB * HH * TT * DH)
__device__ __nv_bfloat16 g_q_h[QKV_ELEMS];
__device__ __nv_bfloat16 g_q_l[QKV_ELEMS];
__device__ __nv_bfloat16 g_k_h[QKV_ELEMS];
__device__ __nv_bfloat16 g_k_l[QKV_ELEMS];
__device__ __nv_bfloat16 g_v_h[QKV_ELEMS];
__device__ __nv_bfloat16 g_v_l[QKV_ELEMS];

// ---------------------------------------------------------------------------
// sm_80-portable PTX helpers
// ---------------------------------------------------------------------------
__device__ __forceinline__ uint32_t smem_u32(const void* p) {
    uint32_t a;
    asm("{ .reg .u64 t; cvta.to.shared.u64 t, %1; cvt.u32.u64 %0, t; }"
        : "=r"(a) : "l"(p));
    return a;
}
__device__ __forceinline__ void cpa16(uint32_t dst, const void* src) {
    asm volatile("cp.async.cg.shared.global [%0], [%1], 16;"
                 :: "r"(dst), "l"(src));
}
__device__ __forceinline__ void cpa4(uint32_t dst, const void* src) {
    asm volatile("cp.async.ca.shared.global [%0], [%1], 4;"
                 :: "r"(dst), "l"(src));
}
#define CP_COMMIT() asm volatile("cp.async.commit_group;" ::: "memory")
#define CP_WAIT(n)  asm volatile("cp.async.wait_group %0;" :: "n"(n) : "memory")

__device__ __forceinline__ void ldsm4(uint32_t* r, uint32_t addr) {
    asm volatile("ldmatrix.sync.aligned.m8n8.x4.shared.b16 {%0,%1,%2,%3}, [%4];"
                 : "=r"(r[0]), "=r"(r[1]), "=r"(r[2]), "=r"(r[3]) : "r"(addr));
}
__device__ __forceinline__ void ldsm4t(uint32_t* r, uint32_t addr) {
    asm volatile("ldmatrix.sync.aligned.m8n8.x4.trans.shared.b16 {%0,%1,%2,%3}, [%4];"
                 : "=r"(r[0]), "=r"(r[1]), "=r"(r[2]), "=r"(r[3]) : "r"(addr));
}
__device__ __forceinline__ void mma_bf16(float* d, const uint32_t* a,
                                         const uint32_t* b) {
    asm volatile("mma.sync.aligned.m16n8k16.row.col.f32.bf16.bf16.f32 "
                 "{%0,%1,%2,%3}, {%4,%5,%6,%7}, {%8,%9}, {%0,%1,%2,%3};"
                 : "+f"(d[0]), "+f"(d[1]), "+f"(d[2]), "+f"(d[3])
                 : "r"(a[0]), "r"(a[1]), "r"(a[2]), "r"(a[3]),
                   "r"(b[0]), "r"(b[1]));
}
// split pair of fp32 -> bf16x2 hi + bf16x2 lo
__device__ __forceinline__ void split2(float x, float y, uint32_t& hi, uint32_t& lo) {
    __nv_bfloat162 h, l;
    h.x = __float2bfloat16(x);
    h.y = __float2bfloat16(y);
    l.x = __float2bfloat16(x - __bfloat162float(h.x));
    l.y = __float2bfloat16(y - __bfloat162float(h.y));
    hi = *(uint32_t*)&h;
    lo = *(uint32_t*)&l;
}

// ---------------------------------------------------------------------------
// Weight pre-split: W[K,N] fp32 -> Wh,Wl [N,K] bf16 (transposed, hi/lo split)
// ---------------------------------------------------------------------------
__global__ void conv_w_kernel(const float* __restrict__ W,
                              __nv_bfloat16* __restrict__ Wh,
                              __nv_bfloat16* __restrict__ Wl, int K, int N)
{
    __shared__ float t[32][33];
    const int n0 = blockIdx.x * 32, k0 = blockIdx.y * 32;
    const int tx = threadIdx.x, ty = threadIdx.y;
    #pragma unroll
    for (int i = 0; i < 32; i += 8)
        t[ty + i][tx] = W[(size_t)(k0 + ty + i) * N + n0 + tx];
    __syncthreads();
    #pragma unroll
    for (int i = 0; i < 32; i += 8) {
        int n = ty + i;
        float v = t[tx][n];
        __nv_bfloat16 h = __float2bfloat16(v);
        __nv_bfloat16 l = __float2bfloat16(v - __bfloat162float(h));
        size_t o = (size_t)(n0 + n) * K + k0 + tx;
        Wh[o] = h;
        Wl[o] = l;
    }
}

// ---------------------------------------------------------------------------
// Activation pre-split: X fp32 [M,K] -> Xh, Xl bf16 [M,K]
// ---------------------------------------------------------------------------
__global__ void conv_a_kernel(const float* __restrict__ X,
                              __nv_bfloat16* __restrict__ Xh,
                              __nv_bfloat16* __restrict__ Xl, int n4)
{
    int idx = blockIdx.x * blockDim.x + threadIdx.x;
    if (idx >= n4) return;
    float4 v = ((const float4*)X)[idx];
    uint32_t h0, h1, l0, l1;
    split2(v.x, v.y, h0, l0);
    split2(v.z, v.w, h1, l1);
    ((uint32_t*)Xh)[idx * 2 + 0] = h0;
    ((uint32_t*)Xh)[idx * 2 + 1] = h1;
    ((uint32_t*)Xl)[idx * 2 + 0] = l0;
    ((uint32_t*)Xl)[idx * 2 + 1] = l1;
}

// ---------------------------------------------------------------------------
// Tensor-core GEMM via mma.sync (bf16 3-term split, fp32 accumulate)
// Two epilogues: plain C+bias (qh==nullptr), or QKV scatter-split.
// __launch_bounds__(256, 2): cap regs at 128 -> 2 CTAs/SM.
// ---------------------------------------------------------------------------
#define GBK 32
#define AROW 40
#define MAT_BYTES (128 * AROW * 2)
#define ST_A_H 0
#define ST_A_L (1 * MAT_BYTES)
#define ST_B_H (2 * MAT_BYTES)
#define ST_B_L (3 * MAT_BYTES)
#define STAGE_B (4 * MAT_BYTES)
#define GEMM_SMEM (2 * STAGE_B)

__device__ __forceinline__ void gemm_load_chunk(
    uint32_t stBase,
    const __nv_bfloat16* __restrict__ Ah, const __nv_bfloat16* __restrict__ Al,
    const __nv_bfloat16* __restrict__ Bh, const __nv_bfloat16* __restrict__ Bl,
    int bm0, int bn0, int k0, int K, int tid)
{
    const int row = tid >> 1;
    const int kc  = (tid & 1) * 16;
    const size_t ga = (size_t)(bm0 + row) * K + k0 + kc;
    const size_t gb = (size_t)(bn0 + row) * K + k0 + kc;
    const uint32_t so = (uint32_t)(row * 80 + kc * 2);
    cpa16(stBase + ST_A_H + so,      Ah + ga);
    cpa16(stBase + ST_A_H + so + 16, Ah + ga + 8);
    cpa16(stBase + ST_A_L + so,      Al + ga);
    cpa16(stBase + ST_A_L + so + 16, Al + ga + 8);
    cpa16(stBase + ST_B_H + so,      Bh + gb);
    cpa16(stBase + ST_B_H + so + 16, Bh + gb + 8);
    cpa16(stBase + ST_B_L + so,      Bl + gb);
    cpa16(stBase + ST_B_L + so + 16, Bl + gb + 8);
}

__global__ __launch_bounds__(256, 2)
void gemm_tc_kernel(const __nv_bfloat16* __restrict__ Ah,
                    const __nv_bfloat16* __restrict__ Al,
                    const __nv_bfloat16* __restrict__ Bh,
                    const __nv_bfloat16* __restrict__ Bl,
                    const float* __restrict__ bias, float* __restrict__ C,
                    int M, int N, int K,
                    __nv_bfloat16* qh, __nv_bfloat16* ql,
                    __nv_bfloat16* kh, __nv_bfloat16* kl,
                    __nv_bfloat16* vh, __nv_bfloat16* vl)
{
    extern __shared__ char smraw[];
    const uint32_t sb = smem_u32(smraw);
    const int tid = threadIdx.x, wid = tid >> 5, lane = tid & 31;
    const int bm0 = blockIdx.y * 128, bn0 = blockIdx.x * 128;
    const int wm = wid >> 2, wn = wid & 3;

    const int a_r = (lane & 7) + ((lane >> 3) & 1) * 8;
    const int a_k = (lane >> 4) * 8;
    const int b_r = (lane & 7) + (lane >> 4) * 8;
    const int b_k = ((lane >> 3) & 1) * 8;

    float acc[4][4][4];
    #pragma unroll
    for (int i = 0; i < 4; i++)
        #pragma unroll
        for (int j = 0; j < 4; j++)
            #pragma unroll
            for (int v = 0; v < 4; v++) acc[i][j][v] = 0.0f;

    const int NCH = K / GBK;

    gemm_load_chunk(sb, Ah, Al, Bh, Bl, bm0, bn0, 0, K, tid);
    CP_COMMIT();

    for (int c = 0; c < NCH; c++) {
        const uint32_t st = sb + (uint32_t)(c & 1) * STAGE_B;
        if (c + 1 < NCH) {
            gemm_load_chunk(sb + (uint32_t)((c + 1) & 1) * STAGE_B,
                            Ah, Al, Bh, Bl, bm0, bn0, (c + 1) * GBK, K, tid);
            CP_COMMIT();
            CP_WAIT(1);
        } else {
            CP_WAIT(0);
        }
        __syncthreads();

        #pragma unroll
        for (int ks = 0; ks < 2; ks++) {
            const int k0 = ks * 16;
            uint32_t bh2[4][2], bl2[4][2];
            #pragma unroll
            for (int half = 0; half < 2; half++) {
                uint32_t baddr = (uint32_t)((wn * 32 + half * 16 + b_r) * 80
                                            + (k0 + b_k) * 2);
                uint32_t r[4];
                ldsm4(r, st + ST_B_H + baddr);
                bh2[half * 2 + 0][0] = r[0]; bh2[half * 2 + 0][1] = r[1];
                bh2[half * 2 + 1][0] = r[2]; bh2[half * 2 + 1][1] = r[3];
                ldsm4(r, st + ST_B_L + baddr);
                bl2[half * 2 + 0][0] = r[0]; bl2[half * 2 + 0][1] = r[1];
                bl2[half * 2 + 1][0] = r[2]; bl2[half * 2 + 1][1] = r[3];
            }
            #pragma unroll
            for (int mi = 0; mi < 4; mi++) {
                uint32_t aaddr = (uint32_t)((wm * 64 + mi * 16 + a_r) * 80
                                            + (k0 + a_k) * 2);
                uint32_t ah[4], al[4];
                ldsm4(ah, st + ST_A_H + aaddr);
                ldsm4(al, st + ST_A_L + aaddr);
                #pragma unroll
                for (int nf = 0; nf < 4; nf++) {
                    mma_bf16(acc[mi][nf], ah, bh2[nf]);
                    mma_bf16(acc[mi][nf], ah, bl2[nf]);
                    mma_bf16(acc[mi][nf], al, bh2[nf]);
                }
            }
        }
        __syncthreads();
    }

    // Epilogue
    #pragma unroll
    for (int mi = 0; mi < 4; mi++) {
        const int row = bm0 + wm * 64 + mi * 16 + (lane >> 2);
        #pragma unroll
        for (int nf = 0; nf < 4; nf++) {
            const int col = bn0 + wn * 32 + nf * 8 + (lane & 3) * 2;
            const float b0 = bias[col], b1 = bias[col + 1];
            float v0 = acc[mi][nf][0] + b0, v1 = acc[mi][nf][1] + b1;
            float v2 = acc[mi][nf][2] + b0, v3 = acc[mi][nf][3] + b1;
            if (qh == nullptr) {
                float2 p0, p1;
                p0.x = v0; p0.y = v1; p1.x = v2; p1.y = v3;
                *(float2*)&C[(size_t)row * N + col]       = p0;
                *(float2*)&C[(size_t)(row + 8) * N + col] = p1;
            } else {
                // scatter to head-major split QKV
                const int sec = col >> 10;
                const int hh  = (col >> 6) & 15;
                const int d   = col & 63;
                const int bb  = row >> 11;
                const int trow = row & 2047;
                const float sc = (sec == 0) ? 0.125f : 1.0f;
                __nv_bfloat16 *H, *L;
                if (sec == 0)      { H = qh; L = ql; }
                else if (sec == 1) { H = kh; L = kl; }
                else               { H = vh; L = vl; }
                size_t dst = (((size_t)(bb * 16 + hh)) * TT + trow) * 64 + d;
                uint32_t hi, lo;
                split2(v0 * sc, v1 * sc, hi, lo);
                *(uint32_t*)(H + dst) = hi;
                *(uint32_t*)(L + dst) = lo;
                split2(v2 * sc, v3 * sc, hi, lo);
                *(uint32_t*)(H + dst + 8 * 64) = hi;
                *(uint32_t*)(L + dst + 8 * 64) = lo;
            }
        }
    }
}

// ---------------------------------------------------------------------------
// Tensor-core flash attention (bf16 3-term split, fp32 softmax):
//   BM=128 (8 warps x 16 rows), BN=64, DH=64.
//   Smem: 2 regions of 36864B; region 0 holds Q during prologue, then both
//   regions double-buffer K/V. 74.3 KB total -> 2 CTAs/SM.
// ---------------------------------------------------------------------------
#define AVROW 72                       // bf16 row stride (144 B)
#define KQH 0
#define KQL 18432
#define KKH 0
#define KKL 9216
#define KVH 18432
#define KVL 27648
#define ASTAGE 36864
#define AMSK (2 * ASTAGE)              // 73728
#define ATTN_SMEM (AMSK + 512)         // 74240

__device__ __forceinline__ void attn_kvload(
    uint32_t sb, int region, int bh, int n0,
    const __nv_bfloat16* __restrict__ Kh_g, const __nv_bfloat16* __restrict__ Kl_g,
    const __nv_bfloat16* __restrict__ Vh_g, const __nv_bfloat16* __restrict__ Vl_g,
    const int* __restrict__ mask, int b, int tid)
{
    const uint32_t st = sb + (uint32_t)region * ASTAGE;
    const size_t gb = ((size_t)bh * TT + n0) * 64;
    #pragma unroll
    for (int u = 0; u < 2; u++) {
        int idx = tid * 2 + u;
        int row = idx >> 3, ch = idx & 7;
        uint32_t so = (uint32_t)(row * 144 + ch * 16);
        size_t go = gb + row * 64 + ch * 8;
        cpa16(st + KKH + so, Kh_g + go);
        cpa16(st + KKL + so, Kl_g + go);
        cpa16(st + KVH + so, Vh_g + go);
        cpa16(st + KVL + so, Vl_g + go);
    }
    if (tid < 64)
        cpa4(sb + AMSK + (uint32_t)region * 256 + tid * 4,
             mask + (size_t)b * TT + n0 + tid);
}

__global__ __launch_bounds__(256, 2)
void attn_tc_kernel(const __nv_bfloat16* __restrict__ Qh_g,
                    const __nv_bfloat16* __restrict__ Ql_g,
                    const __nv_bfloat16* __restrict__ Kh_g,
                    const __nv_bfloat16* __restrict__ Kl_g,
                    const __nv_bfloat16* __restrict__ Vh_g,
                    const __nv_bfloat16* __restrict__ Vl_g,
                    const int* __restrict__ mask,
                    __nv_bfloat16* __restrict__ Oh_g,
                    __nv_bfloat16* __restrict__ Ol_g)
{
    extern __shared__ char smraw[];
    const uint32_t sb = smem_u32(smraw);
    const int tid = threadIdx.x, wid = tid >> 5, lane = tid & 31;
    const int bh = blockIdx.y;
    const int b = bh >> 4, h = bh & 15;
    const int t0 = blockIdx.x * 128;
    const int wm = wid;   // warp rows: wm*16 .. wm*16+15

    const int a_r = (lane & 7) + ((lane >> 3) & 1) * 8;
    const int a_k = (lane >> 4) * 8;
    const int b_r = (lane & 7) + (lane >> 4) * 8;
    const int b_k = ((lane >> 3) & 1) * 8;
    const int c0base = (lane & 3) * 2;

    // --- prologue: Q tile -> region 0, KV tile 0 -> region 1 ---
    const size_t qbase = ((size_t)bh * TT + t0) * 64;
    #pragma unroll
    for (int i = 0; i < 4; i++) {
        int f = tid + i * 256;
        int row = f >> 3, ch = f & 7;
        uint32_t so = (uint32_t)(row * 144 + ch * 16);
        size_t go = qbase + row * 64 + ch * 8;
        cpa16(sb + KQH + so, Qh_g + go);
        cpa16(sb + KQL + so, Ql_g + go);
    }
    attn_kvload(sb, 1, bh, 0, Kh_g, Kl_g, Vh_g, Vl_g, mask, b, tid);
    CP_COMMIT();
    CP_WAIT(0);
    __syncthreads();

    // --- Q fragments to registers (4 k16-steps over DH) ---
    uint32_t qfh[4][4], qfl[4][4];
    #pragma unroll
    for (int kk = 0; kk < 4; kk++) {
        uint32_t addr = (uint32_t)(((wm * 16 + a_r) * AVROW + kk * 16 + a_k) * 2);
        ldsm4(qfh[kk], sb + KQH + addr);
        ldsm4(qfl[kk], sb + KQL + addr);
    }
    __syncthreads();   // all warps done reading Q before region 0 is reused

    float O[8][4];
    #pragma unroll
    for (int j = 0; j < 8; j++)
        #pragma unroll
        for (int v = 0; v < 4; v++) O[j][v] = 0.0f;
    float m0 = -3.0e38f, m1 = -3.0e38f, l0 = 0.0f, l1 = 0.0f;

    for (int t = 0; t < TT / 64; t++) {
        const int rt = (t + 1) & 1;       // region holding tile t
        if (t + 1 < TT / 64) {
            attn_kvload(sb, t & 1, bh, (t + 1) * 64,
                        Kh_g, Kl_g, Vh_g, Vl_g, mask, b, tid);
            CP_COMMIT();
        }
        const uint32_t st = sb + (uint32_t)rt * ASTAGE;
        const int* msk = (const int*)(smraw + AMSK + rt * 256);

        // --- S = Q K^T (scaled Q), 3-term split ---
        float acc[8][4];
        #pragma unroll
        for (int j = 0; j < 8; j++)
            #pragma unroll
            for (int v = 0; v < 4; v++) acc[j][v] = 0.0f;

        #pragma unroll
        for (int kk = 0; kk < 4; kk++) {
            #pragma unroll
            for (int nb = 0; nb < 4; nb++) {
                uint32_t addr = (uint32_t)(((nb * 16 + b_r) * AVROW
                                            + kk * 16 + b_k) * 2);
                uint32_t rh[4], rl[4];
                ldsm4(rh, st + KKH + addr);
                ldsm4(rl, st + KKL + addr);
                mma_bf16(acc[2 * nb],     qfh[kk], &rh[0]);
                mma_bf16(acc[2 * nb],     qfh[kk], &rl[0]);
                mma_bf16(acc[2 * nb],     qfl[kk], &rh[0]);
                mma_bf16(acc[2 * nb + 1], qfh[kk], &rh[2]);
                mma_bf16(acc[2 * nb + 1], qfh[kk], &rl[2]);
                mma_bf16(acc[2 * nb + 1], qfl[kk], &rh[2]);
            }
        }

        // --- mask + online softmax ---
        float rmax0 = -3.0e38f, rmax1 = -3.0e38f;
        #pragma unroll
        for (int j = 0; j < 8; j++) {
            int c = j * 8 + c0base;
            int mk0 = msk[c], mk1 = msk[c + 1];
            acc[j][0] = mk0 ? acc[j][0] : -1000.0f;
            acc[j][1] = mk1 ? acc[j][1] : -1000.0f;
            acc[j][2] = mk0 ? acc[j][2] : -1000.0f;
            acc[j][3] = mk1 ? acc[j][3] : -1000.0f;
            rmax0 = fmaxf(rmax0, fmaxf(acc[j][0], acc[j][1]));
            rmax1 = fmaxf(rmax1, fmaxf(acc[j][2], acc[j][3]));
        }
        rmax0 = fmaxf(rmax0, __shfl_xor_sync(0xffffffffu, rmax0, 1));
        rmax0 = fmaxf(rmax0, __shfl_xor_sync(0xffffffffu, rmax0, 2));
        rmax1 = fmaxf(rmax1, __shfl_xor_sync(0xffffffffu, rmax1, 1));
        rmax1 = fmaxf(rmax1, __shfl_xor_sync(0xffffffffu, rmax1, 2));

        float mn0 = fmaxf(m0, rmax0), mn1 = fmaxf(m1, rmax1);
        float al0 = __expf(m0 - mn0), al1 = __expf(m1 - mn1);
        m0 = mn0; m1 = mn1;

        float rs0 = 0.0f, rs1 = 0.0f;
        #pragma unroll
        for (int j = 0; j < 8; j++) {
            acc[j][0] = __expf(acc[j][0] - mn0); rs0 += acc[j][0];
            acc[j][1] = __expf(acc[j][1] - mn0); rs0 += acc[j][1];
            acc[j][2] = __expf(acc[j][2] - mn1); rs1 += acc[j][2];
            acc[j][3] = __expf(acc[j][3] - mn1); rs1 += acc[j][3];
        }
        rs0 += __shfl_xor_sync(0xffffffffu, rs0, 1);
        rs0 += __shfl_xor_sync(0xffffffffu, rs0, 2);
        rs1 += __shfl_xor_sync(0xffffffffu, rs1, 1);
        rs1 += __shfl_xor_sync(0xffffffffu, rs1, 2);
        l0 = l0 * al0 + rs0;
        l1 = l1 * al1 + rs1;
        #pragma unroll
        for (int j = 0; j < 8; j++) {
            O[j][0] *= al0; O[j][1] *= al0;
            O[j][2] *= al1; O[j][3] *= al1;
        }

        // --- O += P V (3-term split), V frags via ldmatrix.trans ---
        #pragma unroll
        for (int kk = 0; kk < 4; kk++) {
            uint32_t pah[4], pal[4];
            split2(acc[2 * kk][0],     acc[2 * kk][1],     pah[0], pal[0]);
            split2(acc[2 * kk][2],     acc[2 * kk][3],     pah[1], pal[1]);
            split2(acc[2 * kk + 1][0], acc[2 * kk + 1][1], pah[2], pal[2]);
            split2(acc[2 * kk + 1][2], acc[2 * kk + 1][3], pah[3], pal[3]);
            #pragma unroll
            for (int nb = 0; nb < 4; nb++) {
                uint32_t addr = (uint32_t)(((kk * 16 + ((lane >> 3) & 1) * 8
                                             + (lane & 7)) * AVROW
                                            + nb * 16 + (lane >> 4) * 8) * 2);
                uint32_t vh4[4], vl4[4];
                ldsm4t(vh4, st + KVH + addr);
                ldsm4t(vl4, st + KVL + addr);
                mma_bf16(O[2 * nb],     pah, &vh4[0]);
                mma_bf16(O[2 * nb],     pah, &vl4[0]);
                mma_bf16(O[2 * nb],     pal, &vh4[0]);
                mma_bf16(O[2 * nb + 1], pah, &vh4[2]);
                mma_bf16(O[2 * nb + 1], pah, &vl4[2]);
                mma_bf16(O[2 * nb + 1], pal, &vh4[2]);
            }
        }

        if (t + 1 < TT / 64) CP_WAIT(0);
        __syncthreads();
    }

    // --- normalize + write pre-split output (GEMM2 A layout [M,1024]) ---
    const float inv0 = 1.0f / l0, inv1 = 1.0f / l1;
    const int trow = t0 + wm * 16 + (lane >> 2);
    const size_t ob0 = ((size_t)(b * TT + trow)) * DD + h * 64;
    const size_t ob1 = ob0 + (size_t)8 * DD;
    #pragma unroll
    for (int jn = 0; jn < 8; jn++) {
        int c = jn * 8 + c0base;
        uint32_t hi, lo;
        split2(O[jn][0] * inv0, O[jn][1] * inv0, hi, lo);
        *(uint32_t*)(Oh_g + ob0 + c) = hi;
        *(uint32_t*)(Ol_g + ob0 + c) = lo;
        split2(O[jn][2] * inv1, O[jn][3] * inv1, hi, lo);
        *(uint32_t*)(Oh_g + ob1 + c) = hi;
        *(uint32_t*)(Ol_g + ob1 + c) = lo;
    }
}

// ---------------------------------------------------------------------------
extern "C" void kernel_launch(void* const* d_in, const int* in_sizes, int n_in,
                              void* d_out, int out_size)
{
    const float* x     = (const float*)d_in[0];
    const int*   mask  = (const int*)  d_in[1];
    const float* W_qkv = (const float*)d_in[2];
    const float* b_qkv = (const float*)d_in[3];
    const float* W_out = (const float*)d_in[4];
    const float* b_out = (const float*)d_in[5];
    float* out = (float*)d_out;

    __nv_bfloat16 *wqh, *wql, *woh, *wol, *xh, *xl;
    __nv_bfloat16 *qh, *ql, *kh, *kl, *vh, *vl;
    cudaGetSymbolAddress((void**)&wqh, g_wqkv_h);
    cudaGetSymbolAddress((void**)&wql, g_wqkv_l);
    cudaGetSymbolAddress((void**)&woh, g_wout_h);
    cudaGetSymbolAddress((void**)&wol, g_wout_l);
    cudaGetSymbolAddress((void**)&xh,  g_act_h);
    cudaGetSymbolAddress((void**)&xl,  g_act_l);
    cudaGetSymbolAddress((void**)&qh,  g_q_h);
    cudaGetSymbolAddress((void**)&ql,  g_q_l);
    cudaGetSymbolAddress((void**)&kh,  g_k_h);
    cudaGetSymbolAddress((void**)&kl,  g_k_l);
    cudaGetSymbolAddress((void**)&vh,  g_v_h);
    cudaGetSymbolAddress((void**)&vl,  g_v_l);

    cudaFuncSetAttribute(gemm_tc_kernel,
                         cudaFuncAttributeMaxDynamicSharedMemorySize, GEMM_SMEM);
    cudaFuncSetAttribute(attn_tc_kernel,
                         cudaFuncAttributeMaxDynamicSharedMemorySize, ATTN_SMEM);

    const int n4 = MTOT * DD / 4;

    // 0) Pre-split weights (transposed [N,K]) and input activations
    conv_w_kernel<<<dim3(N_QKV / 32, DD / 32), dim3(32, 8)>>>(W_qkv, wqh, wql, DD, N_QKV);
    conv_w_kernel<<<dim3(DD / 32, DD / 32),   dim3(32, 8)>>>(W_out, woh, wol, DD, DD);
    conv_a_kernel<<<(n4 + 255) / 256, 256>>>(x, xh, xl, n4);

    // 1) QKV projection; epilogue scatters split Q/K/V head-major (Q pre-scaled)
    gemm_tc_kernel<<<dim3(N_QKV / 128, MTOT / 128), 256, GEMM_SMEM>>>(
        xh, xl, wqh, wql, b_qkv, nullptr, MTOT, N_QKV, DD,
        qh, ql, kh, kl, vh, vl);

    // 2) Tensor-core flash attention; writes pre-split activations for GEMM2
    attn_tc_kernel<<<dim3(TT / 128, BB * HH), 256, ATTN_SMEM>>>(
        qh, ql, kh, kl, vh, vl, mask, xh, xl);

    // 3) Output projection
    gemm_tc_kernel<<<dim3(DD / 128, MTOT / 128), 256, GEMM_SMEM>>>(
        xh, xl, woh, wol, b_out, out, MTOT, DD, DD,
        nullptr, nullptr, nullptr, nullptr, nullptr, nullptr);
}